// round 8
// baseline (speedup 1.0000x reference)
#include <cuda_runtime.h>
#include <math.h>

#define S_SAMPLES 512
#define VDIM      128
#define NVOX      (VDIM * VDIM * VDIM)   // 2097152
#define NWORDS    (NVOX / 32)            // 65536 words per volume
#define DET       128
#define NPIX      (DET * DET)            // 16384

// 4 binary occupancy BITMAPS, slice = batch*2 + view (view 0=frontal, 1=lateral).
// All share natural layout: word = (vx*128 + vy)*4 + vz/32, bit = vz&31.
// So gt float index = 32*word + bit (exact match with vol_gt_3d layout).
// Invariant: g_bits is all-zero at entry to kernel_launch (static init + the
// reduce kernel consumes-and-rezeroes every word it reads).
__device__ unsigned int g_bits[4][NWORDS];   // 1 MB total
__device__ double       g_acc = 0.0;
__device__ unsigned int g_ctr = 0;

// ---------------------------------------------------------------------------
// Backprojection: one thread per ray; clip sample range to the voxel box,
// march IN VOXEL SPACE (q(t) affine in t), set bits via register-accumulated
// atomicOr (REDG.OR, no return). Frontal rays advance mainly in vz -> the
// current word persists ~12 iters -> ~12x fewer atomics.
// ---------------------------------------------------------------------------
__global__ void bp_kernel(const float* __restrict__ predF,
                          const float* __restrict__ predL,
                          const float* __restrict__ srcF,
                          const float* __restrict__ tgtF,
                          const float* __restrict__ srcL,
                          const float* __restrict__ tgtL,
                          const float* __restrict__ Ainv,
                          const float* __restrict__ tinv)
{
    int p = blockIdx.x * blockDim.x + threadIdx.x;
    if (p >= NPIX) return;
    int slice = blockIdx.y;          // 0..3
    int view  = slice & 1;           // 0 = frontal, 1 = lateral
    int batch = slice >> 1;

    const float* mask = (view ? predL : predF) + batch * NPIX;
    if (!(mask[p] > 0.5f)) return;   // inactive pixel: nothing to do

    const float* src = view ? srcL : srcF;
    const float* tgt = (view ? tgtL : tgtF) + 3 * p;

    float sx = src[0], sy = src[1], sz = src[2];
    float dx = tgt[0] - sx, dy = tgt[1] - sy, dz = tgt[2] - sz;
    float len = sqrtf(dx * dx + dy * dy + dz * dz);
    float inv = 1.0f / (len + 1e-8f);
    dx *= inv; dy *= inv; dz *= inv;
    float L = len * 2.5f;

    float a00 = Ainv[0], a01 = Ainv[1], a02 = Ainv[2];
    float a10 = Ainv[3], a11 = Ainv[4], a12 = Ainv[5];
    float a20 = Ainv[6], a21 = Ainv[7], a22 = Ainv[8];

    // Voxel-space ray: q(t) = q0 + t*qd   (affine in t)
    float q0x = a00 * sx + a01 * sy + a02 * sz + tinv[0];
    float q0y = a10 * sx + a11 * sy + a12 * sz + tinv[1];
    float q0z = a20 * sx + a21 * sy + a22 * sz + tinv[2];
    float qdx = a00 * dx + a01 * dy + a02 * dz;
    float qdy = a10 * dx + a11 * dy + a12 * dz;
    float qdz = a20 * dx + a21 * dy + a22 * dz;

    const float LOQ = -0.501f;                  // round() valid window with margin
    const float HIQ = (float)VDIM - 0.499f;
    float tlo = 0.0f, thi = L;
    {
        float q0a[3] = {q0x, q0y, q0z};
        float qda[3] = {qdx, qdy, qdz};
        #pragma unroll
        for (int ax = 0; ax < 3; ax++) {
            float q0 = q0a[ax], qd = qda[ax];
            if (fabsf(qd) < 1e-9f) {
                if (q0 < LOQ || q0 > HIQ) { tlo = 1.0f; thi = 0.0f; }
            } else {
                float u1 = (LOQ - q0) / qd;
                float u2 = (HIQ - q0) / qd;
                tlo = fmaxf(tlo, fminf(u1, u2));
                thi = fminf(thi, fmaxf(u1, u2));
            }
        }
    }
    if (thi < tlo) return;

    float dt = L * (1.0f / (S_SAMPLES - 1));
    int klo = max(0,             (int)floorf(tlo / dt) - 2);   // safety margin:
    int khi = min(S_SAMPLES - 1, (int)ceilf (thi / dt) + 2);   // per-sample check authoritative

    // Pre-scale direction by L: q = fma(tv, rd, q0), tv = k/(S-1)
    float rdx = L * qdx, rdy = L * qdy, rdz = L * qdz;
    const float c1 = 1.0f / (S_SAMPLES - 1);

    unsigned int* bits = g_bits[slice];
    int prevw = -1;
    unsigned int acc = 0u;
    for (int k = klo; k <= khi; k++) {
        float tv = (float)k * c1;                      // matches jnp.linspace(0,1,S)
        int vx = __float2int_rn(fmaf(tv, rdx, q0x));   // F2I.rn = ties-to-even (jnp.round)
        int vy = __float2int_rn(fmaf(tv, rdy, q0y));
        int vz = __float2int_rn(fmaf(tv, rdz, q0z));
        if ((unsigned)vx < (unsigned)VDIM &&
            (unsigned)vy < (unsigned)VDIM &&
            (unsigned)vz < (unsigned)VDIM) {
            int word = ((vx << 7) + vy) * 4 + (vz >> 5);
            unsigned int b = 1u << (vz & 31);
            if (word == prevw) {
                acc |= b;                              // same word: accumulate locally
            } else {
                if (prevw >= 0) atomicOr(&bits[prevw], acc);   // REDG.OR flush
                prevw = word;
                acc = b;
            }
        }
    }
    if (prevw >= 0) atomicOr(&bits[prevw], acc);
}

// ---------------------------------------------------------------------------
// BCE + finalize + bitmap re-zero, fused. 256 blocks x 256 threads; one
// thread per 32-voxel word (65536 words).
//
// Exact decomposition (sF, sL binary, per batch):
//   b[sF+sL] + g*(sF+sL) = B0 + (sF+sL)*(CC + g) + KAPPA*(sF & sL)
// Summed:  2*NVOX*B0 + CC*popc(all 4 words) + KAPPA*(popc(F0&L0)+popc(F1&L1))
//          + sum_k g_k * n_k   (n_k = total set bits at voxel k across 4 maps)
// B0*(2*NVOX) is folded into the finalizer.
//
// Per thread: 4 word loads + 8 contiguous float4 gt loads up front (MLP 12),
// then pure register math. Every word read is immediately re-zeroed.
// ---------------------------------------------------------------------------
#define CC_F    (-0.62011450695827750f)   // b1 - b0
#define KAPPA_F (-0.19355181656647243f)   // b2 - 2*b1 + b0
#define B0_D    (-0.69314718055994531)    // log(0.5)

__device__ __forceinline__ float warp_sum(float v) {
    #pragma unroll
    for (int o = 16; o > 0; o >>= 1) v += __shfl_down_sync(0xffffffffu, v, o);
    return v;
}

__global__ void __launch_bounds__(256)
reduce_kernel(const float* __restrict__ gt, float* __restrict__ out)
{
    __shared__ float sh[8];
    int w32 = blockIdx.x * 256 + threadIdx.x;      // word index 0..65535

    // ---- issue all loads up front (MLP 12) --------------------------------
    unsigned int F0 = g_bits[0][w32];
    unsigned int L0 = g_bits[1][w32];
    unsigned int F1 = g_bits[2][w32];
    unsigned int L1 = g_bits[3][w32];
    float4 gv[8];
    const float4* gp = reinterpret_cast<const float4*>(gt) + w32 * 8;
    #pragma unroll
    for (int q = 0; q < 8; q++) gv[q] = gp[q];     // 128 contiguous bytes

    // ---- consume-and-reset ------------------------------------------------
    g_bits[0][w32] = 0u;
    g_bits[1][w32] = 0u;
    g_bits[2][w32] = 0u;
    g_bits[3][w32] = 0u;

    // ---- compute ----------------------------------------------------------
    int bcnt = __popc(F0) + __popc(L0) + __popc(F1) + __popc(L1);
    int icnt = __popc(F0 & L0) + __popc(F1 & L1);
    float gsum = 0.0f;
    #pragma unroll
    for (int q = 0; q < 8; q++) {
        int k = q * 4;
        float4 g = gv[q];
        gsum = fmaf(g.x, (float)(((F0 >> (k+0)) & 1u) + ((L0 >> (k+0)) & 1u) +
                                 ((F1 >> (k+0)) & 1u) + ((L1 >> (k+0)) & 1u)), gsum);
        gsum = fmaf(g.y, (float)(((F0 >> (k+1)) & 1u) + ((L0 >> (k+1)) & 1u) +
                                 ((F1 >> (k+1)) & 1u) + ((L1 >> (k+1)) & 1u)), gsum);
        gsum = fmaf(g.z, (float)(((F0 >> (k+2)) & 1u) + ((L0 >> (k+2)) & 1u) +
                                 ((F1 >> (k+2)) & 1u) + ((L1 >> (k+2)) & 1u)), gsum);
        gsum = fmaf(g.w, (float)(((F0 >> (k+3)) & 1u) + ((L0 >> (k+3)) & 1u) +
                                 ((F1 >> (k+3)) & 1u) + ((L1 >> (k+3)) & 1u)), gsum);
    }
    float sum = fmaf(CC_F, (float)bcnt, fmaf(KAPPA_F, (float)icnt, gsum));

    // ---- block reduce -> global atomic -> last-block finalize -------------
    sum = warp_sum(sum);
    int lane = threadIdx.x & 31, w = threadIdx.x >> 5;
    if (lane == 0) sh[w] = sum;
    __syncthreads();
    if (w == 0) {
        float v = (lane < 8) ? sh[lane] : 0.0f;
        v = warp_sum(v);
        if (lane == 0) {
            atomicAdd(&g_acc, (double)v);
            __threadfence();
            unsigned int done = atomicInc(&g_ctr, gridDim.x - 1);   // self-resetting
            if (done == gridDim.x - 1) {
                double acc = atomicAdd(&g_acc, 0.0);                // atomic read
                // loss = -( 2*NVOX*B0 + acc ) / (2*NVOX) = -B0 - acc/(2*NVOX)
                out[0] = (float)(-B0_D - acc / (2.0 * (double)NVOX));
                g_acc = 0.0;                                        // reset for next call
            }
        }
    }
}

// ---------------------------------------------------------------------------
extern "C" void kernel_launch(void* const* d_in, const int* in_sizes, int n_in,
                              void* d_out, int out_size)
{
    const float* predF = (const float*)d_in[0];
    const float* predL = (const float*)d_in[1];
    const float* srcF  = (const float*)d_in[2];
    const float* tgtF  = (const float*)d_in[3];
    const float* srcL  = (const float*)d_in[4];
    const float* tgtL  = (const float*)d_in[5];
    const float* gt    = (const float*)d_in[6];
    const float* Ainv  = (const float*)d_in[7];
    const float* tinv  = (const float*)d_in[8];
    float* out = (float*)d_out;

    dim3 bp_grid((NPIX + 255) / 256, 4);      // 64 x 4 = 256 blocks
    bp_kernel<<<bp_grid, 256>>>(predF, predL, srcF, tgtF, srcL, tgtL, Ainv, tinv);

    reduce_kernel<<<NWORDS / 256, 256>>>(gt, out);   // 256 blocks x 256 threads
}

// round 9
// speedup vs baseline: 1.1908x; 1.1908x over previous
#include <cuda_runtime.h>
#include <math.h>

#define S_SAMPLES 512
#define VDIM      128
#define NVOX      (VDIM * VDIM * VDIM)   // 2097152
#define NWORDS    (NVOX / 32)            // 65536 words per volume
#define DET       128
#define NPIX      (DET * DET)            // 16384

// 4 binary occupancy BITMAPS, slice = batch*2 + view (view 0=frontal, 1=lateral).
// Natural layout for all: word = (vx*128 + vy)*4 + vz/32, bit = vz&31.
// gt float index = 32*word + bit (exact match with vol_gt_3d layout).
// Invariant: g_bits is all-zero at entry to kernel_launch (static init + the
// reduce kernel consumes-and-rezeroes every word it reads).
__device__ unsigned int g_bits[4][NWORDS];   // 1 MB total
__device__ double       g_acc = 0.0;
__device__ unsigned int g_ctr = 0;

// ---------------------------------------------------------------------------
// Backprojection. Frontal rays march vz (bit axis): per-lane register
// accumulation -> ~1 REDG.OR per 12 samples, lanes hit distinct words.
// Lateral rays march vx with lanes sharing words (consecutive vz): use a
// warp-segmented OR (contiguous equal-word runs merged by a conditional
// butterfly; run leaders issue the REDG) -> 1-4 spread atomics/warp/iter
// instead of up-to-32 same-address ones (the R8 disaster).
// ---------------------------------------------------------------------------
__global__ void bp_kernel(const float* __restrict__ predF,
                          const float* __restrict__ predL,
                          const float* __restrict__ srcF,
                          const float* __restrict__ tgtF,
                          const float* __restrict__ srcL,
                          const float* __restrict__ tgtL,
                          const float* __restrict__ Ainv,
                          const float* __restrict__ tinv)
{
    int p = blockIdx.x * blockDim.x + threadIdx.x;   // always < NPIX (exact grid)
    int slice = blockIdx.y;          // 0..3
    int view  = slice & 1;           // 0 = frontal, 1 = lateral
    int batch = slice >> 1;

    const float* mask = (view ? predL : predF) + batch * NPIX;
    bool active = mask[p] > 0.5f;
    if (view == 0 && !active) return;        // frontal path is per-lane independent

    const float* src = view ? srcL : srcF;
    const float* tgt = (view ? tgtL : tgtF) + 3 * p;

    float sx = src[0], sy = src[1], sz = src[2];
    float dx = tgt[0] - sx, dy = tgt[1] - sy, dz = tgt[2] - sz;
    float len = sqrtf(dx * dx + dy * dy + dz * dz);
    float inv = 1.0f / (len + 1e-8f);
    dx *= inv; dy *= inv; dz *= inv;
    float L = len * 2.5f;

    float a00 = Ainv[0], a01 = Ainv[1], a02 = Ainv[2];
    float a10 = Ainv[3], a11 = Ainv[4], a12 = Ainv[5];
    float a20 = Ainv[6], a21 = Ainv[7], a22 = Ainv[8];

    // Voxel-space ray: q(t) = q0 + t*qd   (affine in t)
    float q0x = a00 * sx + a01 * sy + a02 * sz + tinv[0];
    float q0y = a10 * sx + a11 * sy + a12 * sz + tinv[1];
    float q0z = a20 * sx + a21 * sy + a22 * sz + tinv[2];
    float qdx = a00 * dx + a01 * dy + a02 * dz;
    float qdy = a10 * dx + a11 * dy + a12 * dz;
    float qdz = a20 * dx + a21 * dy + a22 * dz;

    const float LOQ = -0.501f;                  // round() valid window with margin
    const float HIQ = (float)VDIM - 0.499f;
    float tlo = 0.0f, thi = L;
    {
        float q0a[3] = {q0x, q0y, q0z};
        float qda[3] = {qdx, qdy, qdz};
        #pragma unroll
        for (int ax = 0; ax < 3; ax++) {
            float q0 = q0a[ax], qd = qda[ax];
            if (fabsf(qd) < 1e-9f) {
                if (q0 < LOQ || q0 > HIQ) { tlo = 1.0f; thi = 0.0f; }
            } else {
                float u1 = (LOQ - q0) / qd;
                float u2 = (HIQ - q0) / qd;
                tlo = fmaxf(tlo, fminf(u1, u2));
                thi = fminf(thi, fmaxf(u1, u2));
            }
        }
    }
    bool hasr = active && (thi >= tlo);

    float dt = L * (1.0f / (S_SAMPLES - 1));
    int klo = max(0,             (int)floorf(tlo / dt) - 2);   // safety margin:
    int khi = min(S_SAMPLES - 1, (int)ceilf (thi / dt) + 2);   // per-sample check authoritative

    float rdx = L * qdx, rdy = L * qdy, rdz = L * qdz;
    const float c1 = 1.0f / (S_SAMPLES - 1);
    unsigned int* bits = g_bits[slice];

    if (view == 0) {
        // ---------------- frontal: per-lane register accumulation ----------
        if (!hasr) return;
        int prevw = -1;
        unsigned int acc = 0u;
        for (int k = klo; k <= khi; k++) {
            float tv = (float)k * c1;                      // jnp.linspace(0,1,S)
            int vx = __float2int_rn(fmaf(tv, rdx, q0x));   // ties-to-even = jnp.round
            int vy = __float2int_rn(fmaf(tv, rdy, q0y));
            int vz = __float2int_rn(fmaf(tv, rdz, q0z));
            if ((unsigned)vx < (unsigned)VDIM &&
                (unsigned)vy < (unsigned)VDIM &&
                (unsigned)vz < (unsigned)VDIM) {
                int word = (((vx << 7) + vy) << 2) + (vz >> 5);
                unsigned int b = 1u << (vz & 31);
                if (word == prevw) {
                    acc |= b;
                } else {
                    if (prevw >= 0) atomicOr(&bits[prevw], acc);   // REDG.OR
                    prevw = word;
                    acc = b;
                }
            }
        }
        if (prevw >= 0) atomicOr(&bits[prevw], acc);
    } else {
        // ---------------- lateral: warp-segmented OR -----------------------
        // No early returns below: all 32 lanes stay converged for shuffles.
        int klo_p = hasr ? klo : 0x7fffffff;
        int khi_p = hasr ? khi : (-0x7fffffff - 1);
        int wklo = klo_p, wkhi = khi_p;
        #pragma unroll
        for (int o = 16; o > 0; o >>= 1) {
            wklo = min(wklo, __shfl_xor_sync(0xffffffffu, wklo, o));
            wkhi = max(wkhi, __shfl_xor_sync(0xffffffffu, wkhi, o));
        }
        if (wkhi < wklo) return;     // warp-uniform
        int lane = threadIdx.x & 31;

        for (int k = wklo; k <= wkhi; k++) {
            float tv = (float)k * c1;
            int vx = __float2int_rn(fmaf(tv, rdx, q0x));
            int vy = __float2int_rn(fmaf(tv, rdy, q0y));
            int vz = __float2int_rn(fmaf(tv, rdz, q0z));
            bool ok = hasr && (k >= klo_p) && (k <= khi_p) &&
                      (unsigned)vx < (unsigned)VDIM &&
                      (unsigned)vy < (unsigned)VDIM &&
                      (unsigned)vz < (unsigned)VDIM;
            int word = ok ? ((((vx << 7) + vy) << 2) + (vz >> 5)) : -1;
            unsigned int bit = ok ? (1u << (vz & 31)) : 0u;
            // Words are monotone across lanes (vz monotone in detector col;
            // rounding preserves order) -> equal-word lanes are contiguous
            // runs. Conditional butterfly ORs each run into its first lane.
            #pragma unroll
            for (int o = 1; o < 32; o <<= 1) {
                int          pw = __shfl_down_sync(0xffffffffu, word, o);
                unsigned int pb = __shfl_down_sync(0xffffffffu, bit,  o);
                if (pw == word) bit |= pb;
            }
            int up = __shfl_up_sync(0xffffffffu, word, 1);
            bool leader = (lane == 0) || (up != word);
            if (leader && word >= 0) atomicOr(&bits[word], bit);   // spread REDG.OR
        }
    }
}

// ---------------------------------------------------------------------------
// BCE + finalize + bitmap re-zero, fused. 512 blocks x 256 threads; one
// thread per HALF-word (16 voxels). The two halves of a word are always
// adjacent lanes of the same warp, so the word load (both lanes) issues
// before the predicated zero-store (lockstep) -> no read/zero race.
//
// Exact decomposition (sF, sL binary, per batch):
//   b[sF+sL] + g*(sF+sL) = B0 + (sF+sL)*(CC + g) + KAPPA*(sF & sL)
// Summed: 2*NVOX*B0 + CC*(total set bits) + KAPPA*(intersections) + sum g*n.
// ---------------------------------------------------------------------------
#define CC_F    (-0.62011450695827750f)   // b1 - b0
#define KAPPA_F (-0.19355181656647243f)   // b2 - 2*b1 + b0
#define B0_D    (-0.69314718055994531)    // log(0.5)

__device__ __forceinline__ float warp_sum(float v) {
    #pragma unroll
    for (int o = 16; o > 0; o >>= 1) v += __shfl_down_sync(0xffffffffu, v, o);
    return v;
}

__global__ void __launch_bounds__(256)
reduce_kernel(const float* __restrict__ gt, float* __restrict__ out)
{
    __shared__ float sh[8];
    int h   = blockIdx.x * 256 + threadIdx.x;   // half-word id 0..131071
    int w32 = h >> 1;
    int sub = h & 1;

    // ---- issue all loads up front (MLP 8) ---------------------------------
    unsigned int F0 = g_bits[0][w32];
    unsigned int L0 = g_bits[1][w32];
    unsigned int F1 = g_bits[2][w32];
    unsigned int L1 = g_bits[3][w32];
    float4 gv[4];
    const float4* gp = reinterpret_cast<const float4*>(gt) + w32 * 8 + sub * 4;
    #pragma unroll
    for (int q = 0; q < 4; q++) gv[q] = gp[q];   // 64 contiguous bytes

    // ---- consume-and-reset (even lane of each pair; warp-lockstep safe) ---
    if (sub == 0) {
        g_bits[0][w32] = 0u;
        g_bits[1][w32] = 0u;
        g_bits[2][w32] = 0u;
        g_bits[3][w32] = 0u;
    }

    // ---- select this thread's 16-bit half ---------------------------------
    int shft = sub << 4;
    F0 = (F0 >> shft) & 0xffffu;
    L0 = (L0 >> shft) & 0xffffu;
    F1 = (F1 >> shft) & 0xffffu;
    L1 = (L1 >> shft) & 0xffffu;

    // ---- compute ----------------------------------------------------------
    int bcnt = __popc(F0) + __popc(L0) + __popc(F1) + __popc(L1);
    int icnt = __popc(F0 & L0) + __popc(F1 & L1);
    float gsum = 0.0f;
    #pragma unroll
    for (int q = 0; q < 4; q++) {
        int k = q * 4;
        float4 g = gv[q];
        gsum = fmaf(g.x, (float)(((F0 >> (k+0)) & 1u) + ((L0 >> (k+0)) & 1u) +
                                 ((F1 >> (k+0)) & 1u) + ((L1 >> (k+0)) & 1u)), gsum);
        gsum = fmaf(g.y, (float)(((F0 >> (k+1)) & 1u) + ((L0 >> (k+1)) & 1u) +
                                 ((F1 >> (k+1)) & 1u) + ((L1 >> (k+1)) & 1u)), gsum);
        gsum = fmaf(g.z, (float)(((F0 >> (k+2)) & 1u) + ((L0 >> (k+2)) & 1u) +
                                 ((F1 >> (k+2)) & 1u) + ((L1 >> (k+2)) & 1u)), gsum);
        gsum = fmaf(g.w, (float)(((F0 >> (k+3)) & 1u) + ((L0 >> (k+3)) & 1u) +
                                 ((F1 >> (k+3)) & 1u) + ((L1 >> (k+3)) & 1u)), gsum);
    }
    float sum = fmaf(CC_F, (float)bcnt, fmaf(KAPPA_F, (float)icnt, gsum));

    // ---- block reduce -> global atomic -> last-block finalize -------------
    sum = warp_sum(sum);
    int lane = threadIdx.x & 31, w = threadIdx.x >> 5;
    if (lane == 0) sh[w] = sum;
    __syncthreads();
    if (w == 0) {
        float v = (lane < 8) ? sh[lane] : 0.0f;
        v = warp_sum(v);
        if (lane == 0) {
            atomicAdd(&g_acc, (double)v);
            __threadfence();
            unsigned int done = atomicInc(&g_ctr, gridDim.x - 1);   // self-resetting
            if (done == gridDim.x - 1) {
                double acc = atomicAdd(&g_acc, 0.0);                // atomic read
                // loss = -( 2*NVOX*B0 + acc ) / (2*NVOX) = -B0 - acc/(2*NVOX)
                out[0] = (float)(-B0_D - acc / (2.0 * (double)NVOX));
                g_acc = 0.0;                                        // reset for next call
            }
        }
    }
}

// ---------------------------------------------------------------------------
extern "C" void kernel_launch(void* const* d_in, const int* in_sizes, int n_in,
                              void* d_out, int out_size)
{
    const float* predF = (const float*)d_in[0];
    const float* predL = (const float*)d_in[1];
    const float* srcF  = (const float*)d_in[2];
    const float* tgtF  = (const float*)d_in[3];
    const float* srcL  = (const float*)d_in[4];
    const float* tgtL  = (const float*)d_in[5];
    const float* gt    = (const float*)d_in[6];
    const float* Ainv  = (const float*)d_in[7];
    const float* tinv  = (const float*)d_in[8];
    float* out = (float*)d_out;

    dim3 bp_grid((NPIX + 255) / 256, 4);      // 64 x 4 = 256 blocks
    bp_kernel<<<bp_grid, 256>>>(predF, predL, srcF, tgtF, srcL, tgtL, Ainv, tinv);

    reduce_kernel<<<512, 256>>>(gt, out);     // 131072 threads, half-word each
}

// round 10
// speedup vs baseline: 1.4250x; 1.1967x over previous
#include <cuda_runtime.h>
#include <math.h>

#define S_SAMPLES 512
#define VDIM      128
#define NVOX      (VDIM * VDIM * VDIM)   // 2097152
#define DET       128
#define NPIX      (DET * DET)            // 16384
#define NBLOCKS   1024                   // must stay <= 148 * 7 for co-residency

// 4 binary occupancy volumes, slice = batch*2 + view (view 0 = frontal, 1 = lateral).
// Frontal volumes use TRANSPOSED layout (vx, vz, vy) so warp-lane scatter stores
// (lanes differ in vy) are contiguous. Lateral volumes use natural (vx, vy, vz)
// (lanes differ in vz -> already contiguous).
// Invariant: g_vol is all-zero at entry to kernel_launch (static init + the
// reduce phase consumes-and-rezeroes every byte it reads).
__device__ __align__(16) unsigned char g_vol[4][NVOX];   // 8 MB
__device__ double       g_acc = 0.0;
__device__ unsigned int g_ctr = 0;
__device__ unsigned int g_bar = 0;       // grid barrier arrivals (reset by finalizer)

#define CC_F    (-0.62011450695827750f)   // b1 - b0
#define KAPPA_F (-0.19355181656647243f)   // b2 - 2*b1 + b0
#define B0_D    (-0.69314718055994531)    // log(0.5)

__device__ __forceinline__ float warp_sum(float v) {
    #pragma unroll
    for (int o = 16; o > 0; o >>= 1) v += __shfl_down_sync(0xffffffffu, v, o);
    return v;
}

#define TROW 68   // smem row stride (vz-half 64 + 4 pad)

// ---------------------------------------------------------------------------
// ONE persistent kernel: phase 1 = backprojection (blocks 0..255, R7 body),
// grid barrier (all 1024 blocks co-resident by __launch_bounds__(256,7)),
// phase 2 = BCE reduce + re-zero + finalize (all 1024 blocks, R7 body).
// Saves one kernel launch + inter-kernel drain; reduce reads L2-hot lines.
// ---------------------------------------------------------------------------
__global__ void __launch_bounds__(256, 7)
fused_kernel(const float* __restrict__ predF,
             const float* __restrict__ predL,
             const float* __restrict__ srcF,
             const float* __restrict__ tgtF,
             const float* __restrict__ srcL,
             const float* __restrict__ tgtL,
             const float* __restrict__ Ainv,
             const float* __restrict__ tinv,
             const float* __restrict__ gt,
             float*       __restrict__ out)
{
    __shared__ unsigned char sT0[32 * TROW];   // frontal batch 0: [vy_local][vz_local]
    __shared__ unsigned char sT1[32 * TROW];   // frontal batch 1
    __shared__ float sh[8];

    int t = threadIdx.x;     // 256 threads
    int b = blockIdx.x;      // 0..1023

    // ======================= phase 1: backprojection =======================
    if (b < 256) {
        int slice = b >> 6;                  // 0..3
        int view  = slice & 1;               // 0 = frontal, 1 = lateral
        int batch = slice >> 1;
        int p = (b & 63) * 256 + t;          // ray 0..16383

        const float* mask = (view ? predL : predF) + batch * NPIX;
        if (mask[p] > 0.5f) {
            const float* src = view ? srcL : srcF;
            const float* tgt = (view ? tgtL : tgtF) + 3 * p;

            float sx = src[0], sy = src[1], sz = src[2];
            float dx = tgt[0] - sx, dy = tgt[1] - sy, dz = tgt[2] - sz;
            float len = sqrtf(dx * dx + dy * dy + dz * dz);
            float inv = 1.0f / (len + 1e-8f);
            dx *= inv; dy *= inv; dz *= inv;
            float L = len * 2.5f;

            float a00 = Ainv[0], a01 = Ainv[1], a02 = Ainv[2];
            float a10 = Ainv[3], a11 = Ainv[4], a12 = Ainv[5];
            float a20 = Ainv[6], a21 = Ainv[7], a22 = Ainv[8];

            // Voxel-space ray: q(t) = q0 + t*qd (affine in t)
            float q0x = a00 * sx + a01 * sy + a02 * sz + tinv[0];
            float q0y = a10 * sx + a11 * sy + a12 * sz + tinv[1];
            float q0z = a20 * sx + a21 * sy + a22 * sz + tinv[2];
            float qdx = a00 * dx + a01 * dy + a02 * dz;
            float qdy = a10 * dx + a11 * dy + a12 * dz;
            float qdz = a20 * dx + a21 * dy + a22 * dz;

            const float LOQ = -0.501f;              // round() valid window + margin
            const float HIQ = (float)VDIM - 0.499f;
            float tlo = 0.0f, thi = L;
            {
                float q0a[3] = {q0x, q0y, q0z};
                float qda[3] = {qdx, qdy, qdz};
                #pragma unroll
                for (int ax = 0; ax < 3; ax++) {
                    float q0 = q0a[ax], qd = qda[ax];
                    if (fabsf(qd) < 1e-9f) {
                        if (q0 < LOQ || q0 > HIQ) { tlo = 1.0f; thi = 0.0f; }
                    } else {
                        float u1 = (LOQ - q0) / qd;
                        float u2 = (HIQ - q0) / qd;
                        tlo = fmaxf(tlo, fminf(u1, u2));
                        thi = fminf(thi, fmaxf(u1, u2));
                    }
                }
            }
            if (thi >= tlo) {
                float dt = L * (1.0f / (S_SAMPLES - 1));
                int klo = max(0,             (int)floorf(tlo / dt) - 2);  // margin;
                int khi = min(S_SAMPLES - 1, (int)ceilf (thi / dt) + 2);  // per-sample check rules

                float rdx = L * qdx, rdy = L * qdy, rdz = L * qdz;
                const float c1 = 1.0f / (S_SAMPLES - 1);

                unsigned char* vol = g_vol[slice];
                for (int k = klo; k <= khi; k++) {
                    float tv = (float)k * c1;                    // jnp.linspace(0,1,S)
                    int vx = __float2int_rn(fmaf(tv, rdx, q0x)); // ties-to-even = jnp.round
                    int vy = __float2int_rn(fmaf(tv, rdy, q0y));
                    int vz = __float2int_rn(fmaf(tv, rdz, q0z));
                    if ((unsigned)vx < (unsigned)VDIM &&
                        (unsigned)vy < (unsigned)VDIM &&
                        (unsigned)vz < (unsigned)VDIM) {
                        // frontal: (vx, vz, vy) transposed; lateral: natural
                        int idx = view ? ((vx * VDIM + vy) * VDIM + vz)
                                       : ((vx * VDIM + vz) * VDIM + vy);
                        vol[idx] = 1;   // idempotent racy store
                    }
                }
            }
        }
    }

    // ======================= grid barrier ==================================
    // All NBLOCKS blocks are co-resident (launch_bounds(256,7): 7/SM * 148 =
    // 1036 >= 1024), so spinning cannot deadlock. Arrive with fence+atomic;
    // wait with plain volatile L2 reads (read broadcast, no RMW serialization).
    __syncthreads();
    if (t == 0) {
        __threadfence();                      // publish bp stores
        atomicAdd(&g_bar, 1u);
        volatile unsigned int* vb = &g_bar;
        while (*vb < (unsigned)NBLOCKS) { __nanosleep(128); }
    }
    __syncthreads();
    __threadfence();                          // order barrier read before vol reads

    // ======================= phase 2: reduce ===============================
    // Flat-decode R7's (vx plane, vy quarter, vz half):
    int vx  = b & 127;
    int vy0 = ((b >> 7) & 3) * 32;
    int vz0 = (b >> 9) * 64;

    // phase-1 mapping: both frontal vols, 64 vz rows x 32 vy bytes
    int volsel = t >> 7;
    int u6  = t & 127;
    int r6  = u6 >> 1;                // vz_local 0..63
    int sub = u6 & 1;
    size_t go = (size_t)vx * 16384 + (size_t)(vz0 + r6) * 128 + vy0 + sub * 16;
    uint4* pF = reinterpret_cast<uint4*>(g_vol[volsel ? 2 : 0] + go);
    uint4 a = *pF;                    // issue frontal load first

    int c  = t & 31;                  // lane
    int w  = t >> 5;                  // warp 0..7
    int vp = c >> 4;                  // vy sub-pair
    int cw = c & 15;                  // vz word within half
    unsigned int l0w[2], l1w[2];
    float4 gv[2];
    int gidx[2];
    int hz = b >> 9;
    #pragma unroll
    for (int ii = 0; ii < 2; ii++) {
        int vyl = w * 4 + 2 * ii + vp;                       // 0..31
        gidx[ii] = vx * 4096 + (vy0 + vyl) * 32 + hz * 16 + cw;
        l0w[ii] = reinterpret_cast<const unsigned int*>(g_vol[1])[gidx[ii]];
        l1w[ii] = reinterpret_cast<const unsigned int*>(g_vol[3])[gidx[ii]];
        gv[ii]  = reinterpret_cast<const float4*>(gt)[gidx[ii]];
    }

    // consume-and-reset: zero every byte we just read
    uint4 z4; z4.x = z4.y = z4.z = z4.w = 0u;
    *pF = z4;
    #pragma unroll
    for (int ii = 0; ii < 2; ii++) {
        reinterpret_cast<unsigned int*>(g_vol[1])[gidx[ii]] = 0u;
        reinterpret_cast<unsigned int*>(g_vol[3])[gidx[ii]] = 0u;
    }

    // smem transpose of frontal (byte column-writes, same-word merge)
    unsigned char ab[16];
    *reinterpret_cast<uint4*>(ab) = a;
    unsigned char* sT = volsel ? sT1 : sT0;
    int vybase = sub * 16;
    #pragma unroll
    for (int i = 0; i < 16; i++) {
        sT[(vybase + i) * TROW + r6] = ab[i];
    }
    __syncthreads();

    // compute (registers + smem only)
    float sum  = 0.0f;
    int   icnt = 0;
    #pragma unroll
    for (int ii = 0; ii < 2; ii++) {
        int vyl = w * 4 + 2 * ii + vp;
        unsigned int f0 = *reinterpret_cast<const unsigned int*>(&sT0[vyl * TROW + 4 * cw]);
        unsigned int f1 = *reinterpret_cast<const unsigned int*>(&sT1[vyl * TROW + 4 * cw]);
        unsigned int s0 = f0 + l0w[ii];          // bytewise sums (each <= 2, no carry)
        unsigned int s1 = f1 + l1w[ii];
        icnt += __popc(f0 & l0w[ii]) + __popc(f1 & l1w[ii]);   // intersections
        float cgx = CC_F + gv[ii].x;
        float cgy = CC_F + gv[ii].y;
        float cgz = CC_F + gv[ii].z;
        float cgw = CC_F + gv[ii].w;
        sum = fmaf((float)( s0        & 255u), cgx, sum);
        sum = fmaf((float)((s0 >>  8) & 255u), cgy, sum);
        sum = fmaf((float)((s0 >> 16) & 255u), cgz, sum);
        sum = fmaf((float)( s0 >> 24        ), cgw, sum);
        sum = fmaf((float)( s1        & 255u), cgx, sum);
        sum = fmaf((float)((s1 >>  8) & 255u), cgy, sum);
        sum = fmaf((float)((s1 >> 16) & 255u), cgz, sum);
        sum = fmaf((float)( s1 >> 24        ), cgw, sum);
    }
    sum = fmaf(KAPPA_F, (float)icnt, sum);

    // block reduce -> global atomic -> last-block finalize
    sum = warp_sum(sum);
    int lane = t & 31;
    if (lane == 0) sh[w] = sum;
    __syncthreads();
    if (w == 0) {
        float v = (lane < 8) ? sh[lane] : 0.0f;
        v = warp_sum(v);
        if (lane == 0) {
            atomicAdd(&g_acc, (double)v);
            __threadfence();
            unsigned int done = atomicInc(&g_ctr, NBLOCKS - 1);   // self-resetting
            if (done == NBLOCKS - 1) {
                double acc = atomicAdd(&g_acc, 0.0);              // atomic read
                // loss = -( 2*NVOX*B0 + acc ) / (2*NVOX) = -B0 - acc/(2*NVOX)
                out[0] = (float)(-B0_D - acc / (2.0 * (double)NVOX));
                g_acc = 0.0;                                      // reset for next call
                g_bar = 0u;                                       // reset grid barrier
            }
        }
    }
}

// ---------------------------------------------------------------------------
extern "C" void kernel_launch(void* const* d_in, const int* in_sizes, int n_in,
                              void* d_out, int out_size)
{
    const float* predF = (const float*)d_in[0];
    const float* predL = (const float*)d_in[1];
    const float* srcF  = (const float*)d_in[2];
    const float* tgtF  = (const float*)d_in[3];
    const float* srcL  = (const float*)d_in[4];
    const float* tgtL  = (const float*)d_in[5];
    const float* gt    = (const float*)d_in[6];
    const float* Ainv  = (const float*)d_in[7];
    const float* tinv  = (const float*)d_in[8];
    float* out = (float*)d_out;

    fused_kernel<<<NBLOCKS, 256>>>(predF, predL, srcF, tgtF, srcL, tgtL,
                                   Ainv, tinv, gt, out);
}

// round 11
// speedup vs baseline: 1.5981x; 1.1215x over previous
#include <cuda_runtime.h>
#include <math.h>

#define S_SAMPLES 512
#define VDIM      128
#define NVOX      (VDIM * VDIM * VDIM)   // 2097152
#define DET       128
#define NPIX      (DET * DET)            // 16384

// 4 binary occupancy volumes, slice = batch*2 + view (view 0 = frontal, 1 = lateral).
// Frontal volumes use TRANSPOSED layout (vx, vz, vy) so warp-lane scatter stores
// (lanes differ in vy) are contiguous. Lateral volumes use natural (vx, vy, vz)
// (lanes differ in vz -> already contiguous).
// Invariant: g_vol is all-zero at entry to kernel_launch (static init + the
// reduce kernel consumes-and-rezeroes every byte it reads).
__device__ __align__(16) unsigned char g_vol[4][NVOX];   // 8 MB
__device__ double       g_acc = 0.0;
__device__ unsigned int g_ctr = 0;

// ---------------------------------------------------------------------------
// Backprojection with ACTIVE-RAY COMPACTION: ~50% of pixels are inactive at
// random, so uncompacted warps waste half their lanes for the whole ~60-iter
// march. Compact active pixel ids into smem (ballot + warp-leader atomic),
// then march with dense warps (threads t < n) -> marching issue load halves.
// ---------------------------------------------------------------------------
__global__ void __launch_bounds__(256)
bp_kernel(const float* __restrict__ predF,
          const float* __restrict__ predL,
          const float* __restrict__ srcF,
          const float* __restrict__ tgtF,
          const float* __restrict__ srcL,
          const float* __restrict__ tgtL,
          const float* __restrict__ Ainv,
          const float* __restrict__ tinv)
{
    __shared__ unsigned short rays[256];
    __shared__ int cnt;

    int t = threadIdx.x;
    int slice = blockIdx.y;          // 0..3
    int view  = slice & 1;           // 0 = frontal, 1 = lateral
    int batch = slice >> 1;
    int p0 = blockIdx.x * 256 + t;   // pixel this thread tests

    const float* mask = (view ? predL : predF) + batch * NPIX;
    bool active = mask[p0] > 0.5f;

    if (t == 0) cnt = 0;
    __syncthreads();

    // ---- compaction: ballot + warp-leader block atomic --------------------
    int lane = t & 31;
    unsigned int bal = __ballot_sync(0xffffffffu, active);
    int base = 0;
    if (lane == 0 && bal) base = atomicAdd_block(&cnt, __popc(bal));
    base = __shfl_sync(0xffffffffu, base, 0);
    if (active) {
        unsigned int ltm = (1u << lane) - 1u;
        rays[base + __popc(bal & ltm)] = (unsigned short)p0;
    }
    __syncthreads();

    int n = cnt;
    if (t >= n) return;              // dense: only warps 0..ceil(n/32)-1 march
    int p = rays[t];

    const float* src = view ? srcL : srcF;
    const float* tgt = (view ? tgtL : tgtF) + 3 * p;

    float sx = src[0], sy = src[1], sz = src[2];
    float dx = tgt[0] - sx, dy = tgt[1] - sy, dz = tgt[2] - sz;
    float len = sqrtf(dx * dx + dy * dy + dz * dz);
    float inv = 1.0f / (len + 1e-8f);
    dx *= inv; dy *= inv; dz *= inv;
    float L = len * 2.5f;

    float a00 = Ainv[0], a01 = Ainv[1], a02 = Ainv[2];
    float a10 = Ainv[3], a11 = Ainv[4], a12 = Ainv[5];
    float a20 = Ainv[6], a21 = Ainv[7], a22 = Ainv[8];

    // Voxel-space ray: q(t) = q0 + t*qd   (affine in t)
    float q0x = a00 * sx + a01 * sy + a02 * sz + tinv[0];
    float q0y = a10 * sx + a11 * sy + a12 * sz + tinv[1];
    float q0z = a20 * sx + a21 * sy + a22 * sz + tinv[2];
    float qdx = a00 * dx + a01 * dy + a02 * dz;
    float qdy = a10 * dx + a11 * dy + a12 * dz;
    float qdz = a20 * dx + a21 * dy + a22 * dz;

    const float LOQ = -0.501f;                  // round() valid window with margin
    const float HIQ = (float)VDIM - 0.499f;
    float tlo = 0.0f, thi = L;
    {
        float q0a[3] = {q0x, q0y, q0z};
        float qda[3] = {qdx, qdy, qdz};
        #pragma unroll
        for (int ax = 0; ax < 3; ax++) {
            float q0 = q0a[ax], qd = qda[ax];
            if (fabsf(qd) < 1e-9f) {
                if (q0 < LOQ || q0 > HIQ) { tlo = 1.0f; thi = 0.0f; }
            } else {
                float u1 = (LOQ - q0) / qd;
                float u2 = (HIQ - q0) / qd;
                tlo = fmaxf(tlo, fminf(u1, u2));
                thi = fminf(thi, fmaxf(u1, u2));
            }
        }
    }
    if (thi < tlo) return;

    float dt = L * (1.0f / (S_SAMPLES - 1));
    int klo = max(0,             (int)floorf(tlo / dt) - 2);   // safety margin:
    int khi = min(S_SAMPLES - 1, (int)ceilf (thi / dt) + 2);   // per-sample check authoritative

    // Pre-scale direction by L: q = fma(tv, rd, q0), tv = k/(S-1)
    float rdx = L * qdx, rdy = L * qdy, rdz = L * qdz;
    const float c1 = 1.0f / (S_SAMPLES - 1);

    unsigned char* vol = g_vol[slice];
    #pragma unroll 2
    for (int k = klo; k <= khi; k++) {
        float tv = (float)k * c1;                      // matches jnp.linspace(0,1,S)
        int vx = __float2int_rn(fmaf(tv, rdx, q0x));   // F2I.rn = ties-to-even (jnp.round)
        int vy = __float2int_rn(fmaf(tv, rdy, q0y));
        int vz = __float2int_rn(fmaf(tv, rdz, q0z));
        if ((unsigned)vx < (unsigned)VDIM &&
            (unsigned)vy < (unsigned)VDIM &&
            (unsigned)vz < (unsigned)VDIM) {
            // view 0 (frontal): transposed (vx, vz, vy) -> lanes contiguous in vy
            // view 1 (lateral): natural    (vx, vy, vz) -> lanes contiguous in vz
            int idx = view ? ((vx * VDIM + vy) * VDIM + vz)
                           : ((vx * VDIM + vz) * VDIM + vy);
            vol[idx] = 1;   // idempotent racy store
        }
    }
}

// ---------------------------------------------------------------------------
// BCE + finalize + volume re-zero, fused (R7 body, unchanged — best measured).
// 256 threads, grid (128, 4, 2): block = (vx plane, vy quarter, vz half).
//
// Exact decomposition (sF, sL binary):
//   b[sF+sL] + g*(sF+sL) = B0 + (sF+sL)*(CC + g) + KAPPA*(sF & sL)
// B0*(2*NVOX) folded into the finalizer; intersections counted via popc.
// ALL global loads issued up-front; every byte read is re-zeroed.
// ---------------------------------------------------------------------------
#define CC_F    (-0.62011450695827750f)   // b1 - b0
#define KAPPA_F (-0.19355181656647243f)   // b2 - 2*b1 + b0
#define B0_D    (-0.69314718055994531)    // log(0.5)

__device__ __forceinline__ float warp_sum(float v) {
    #pragma unroll
    for (int o = 16; o > 0; o >>= 1) v += __shfl_down_sync(0xffffffffu, v, o);
    return v;
}

#define TROW 68   // smem row stride (vz-half 64 + 4 pad)

__global__ void __launch_bounds__(256)
reduce_kernel(const float* __restrict__ gt, float* __restrict__ out)
{
    __shared__ unsigned char sT0[32 * TROW];   // frontal batch 0: [vy_local][vz_local]
    __shared__ unsigned char sT1[32 * TROW];   // frontal batch 1
    __shared__ float sh[8];

    int vx  = blockIdx.x;            // plane
    int vy0 = blockIdx.y * 32;       // vy quarter
    int vz0 = blockIdx.z * 64;       // vz half
    int t   = threadIdx.x;           // 256 threads

    // ---- phase-1 mapping: both frontal vols, 64 vz rows x 32 vy bytes ------
    int volsel = t >> 7;
    int u   = t & 127;
    int r6  = u >> 1;                // vz_local 0..63
    int sub = u & 1;
    size_t go = (size_t)vx * 16384 + (size_t)(vz0 + r6) * 128 + vy0 + sub * 16;
    uint4* pF = reinterpret_cast<uint4*>(g_vol[volsel ? 2 : 0] + go);
    uint4 a = *pF;                   // issue frontal load first

    // ---- phase-2 mapping + issue lateral/gt loads (max MLP) ----------------
    int c  = t & 31;                 // lane
    int w  = t >> 5;                 // warp 0..7
    int vp = c >> 4;                 // vy sub-pair
    int cw = c & 15;                 // vz word within half
    unsigned int l0w[2], l1w[2];
    float4 gv[2];
    int gidx[2];
    #pragma unroll
    for (int ii = 0; ii < 2; ii++) {
        int vyl = w * 4 + 2 * ii + vp;                       // 0..31
        gidx[ii] = vx * 4096 + (vy0 + vyl) * 32 + blockIdx.z * 16 + cw;
        l0w[ii] = reinterpret_cast<const unsigned int*>(g_vol[1])[gidx[ii]];
        l1w[ii] = reinterpret_cast<const unsigned int*>(g_vol[3])[gidx[ii]];
        gv[ii]  = reinterpret_cast<const float4*>(gt)[gidx[ii]];
    }

    // ---- consume-and-reset: zero every byte we just read -------------------
    uint4 z4; z4.x = z4.y = z4.z = z4.w = 0u;
    *pF = z4;
    #pragma unroll
    for (int ii = 0; ii < 2; ii++) {
        reinterpret_cast<unsigned int*>(g_vol[1])[gidx[ii]] = 0u;
        reinterpret_cast<unsigned int*>(g_vol[3])[gidx[ii]] = 0u;
    }

    // ---- smem transpose of frontal (byte column-writes, same-word merge) ---
    unsigned char ab[16];
    *reinterpret_cast<uint4*>(ab) = a;
    unsigned char* sT = volsel ? sT1 : sT0;
    int vybase = sub * 16;
    #pragma unroll
    for (int i = 0; i < 16; i++) {
        sT[(vybase + i) * TROW + r6] = ab[i];
    }
    __syncthreads();

    // ---- compute (registers + smem only) -----------------------------------
    float sum  = 0.0f;
    int   icnt = 0;
    #pragma unroll
    for (int ii = 0; ii < 2; ii++) {
        int vyl = w * 4 + 2 * ii + vp;
        unsigned int f0 = *reinterpret_cast<const unsigned int*>(&sT0[vyl * TROW + 4 * cw]);
        unsigned int f1 = *reinterpret_cast<const unsigned int*>(&sT1[vyl * TROW + 4 * cw]);
        unsigned int s0 = f0 + l0w[ii];          // bytewise sums (each <= 2, no carry)
        unsigned int s1 = f1 + l1w[ii];
        icnt += __popc(f0 & l0w[ii]) + __popc(f1 & l1w[ii]);   // intersections
        float cgx = CC_F + gv[ii].x;
        float cgy = CC_F + gv[ii].y;
        float cgz = CC_F + gv[ii].z;
        float cgw = CC_F + gv[ii].w;
        sum = fmaf((float)( s0        & 255u), cgx, sum);
        sum = fmaf((float)((s0 >>  8) & 255u), cgy, sum);
        sum = fmaf((float)((s0 >> 16) & 255u), cgz, sum);
        sum = fmaf((float)( s0 >> 24        ), cgw, sum);
        sum = fmaf((float)( s1        & 255u), cgx, sum);
        sum = fmaf((float)((s1 >>  8) & 255u), cgy, sum);
        sum = fmaf((float)((s1 >> 16) & 255u), cgz, sum);
        sum = fmaf((float)( s1 >> 24        ), cgw, sum);
    }
    sum = fmaf(KAPPA_F, (float)icnt, sum);

    // ---- block reduce -> global atomic -> last-block finalize --------------
    sum = warp_sum(sum);
    int lane = t & 31;
    if (lane == 0) sh[w] = sum;
    __syncthreads();
    if (w == 0) {
        float v = (lane < 8) ? sh[lane] : 0.0f;
        v = warp_sum(v);
        if (lane == 0) {
            atomicAdd(&g_acc, (double)v);
            __threadfence();
            unsigned int total = gridDim.x * gridDim.y * gridDim.z;
            unsigned int done = atomicInc(&g_ctr, total - 1);   // self-resetting
            if (done == total - 1) {
                double acc = atomicAdd(&g_acc, 0.0);            // atomic read
                // loss = -( 2*NVOX*B0 + acc ) / (2*NVOX) = -B0 - acc/(2*NVOX)
                out[0] = (float)(-B0_D - acc / (2.0 * (double)NVOX));
                g_acc = 0.0;                                    // reset for next call
            }
        }
    }
}

// ---------------------------------------------------------------------------
extern "C" void kernel_launch(void* const* d_in, const int* in_sizes, int n_in,
                              void* d_out, int out_size)
{
    const float* predF = (const float*)d_in[0];
    const float* predL = (const float*)d_in[1];
    const float* srcF  = (const float*)d_in[2];
    const float* tgtF  = (const float*)d_in[3];
    const float* srcL  = (const float*)d_in[4];
    const float* tgtL  = (const float*)d_in[5];
    const float* gt    = (const float*)d_in[6];
    const float* Ainv  = (const float*)d_in[7];
    const float* tinv  = (const float*)d_in[8];
    float* out = (float*)d_out;

    dim3 bp_grid(NPIX / 256, 4);              // 64 x 4 = 256 blocks
    bp_kernel<<<bp_grid, 256>>>(predF, predL, srcF, tgtF, srcL, tgtL, Ainv, tinv);

    dim3 rd_grid(VDIM, 4, 2);                 // 1024 blocks x 256 threads
    reduce_kernel<<<rd_grid, 256>>>(gt, out);
}